// round 2
// baseline (speedup 1.0000x reference)
#include <cuda_runtime.h>

// ---------------- problem dims ----------------
#define NPTS   4096
#define HDIM   64
#define ODIM   16
#define JSPLIT 16
#define TJ     128
#define JRANGE (NPTS / JSPLIT)

typedef unsigned long long ull;

// ---------------- f32x2 helpers (Blackwell packed fp32) ----------------
static __device__ __forceinline__ ull pk(float a, float b) {
    ull r; asm("mov.b64 %0, {%1, %2};" : "=l"(r) : "f"(a), "f"(b)); return r;
}
static __device__ __forceinline__ void upk(ull x, float& a, float& b) {
    asm("mov.b64 {%0, %1}, %2;" : "=f"(a), "=f"(b) : "l"(x));
}
static __device__ __forceinline__ ull fma2(ull a, ull b, ull c) {
    ull d; asm("fma.rn.f32x2 %0, %1, %2, %3;" : "=l"(d) : "l"(a), "l"(b), "l"(c)); return d;
}
static __device__ __forceinline__ ull mul2(ull a, ull b) {
    ull d; asm("mul.rn.f32x2 %0, %1, %2;" : "=l"(d) : "l"(a), "l"(b)); return d;
}
static __device__ __forceinline__ ull add2(ull a, ull b) {
    ull d; asm("add.rn.f32x2 %0, %1, %2;" : "=l"(d) : "l"(a), "l"(b)); return d;
}
static __device__ __forceinline__ float ex2(float x) {
    float r; asm("ex2.approx.f32 %0, %1;" : "=f"(r) : "f"(x)); return r;
}
static __device__ __forceinline__ float leaky(float x) { return fmaxf(x, 0.2f * x); }

static __device__ __forceinline__ float warp_sum(float v) {
    #pragma unroll
    for (int o = 16; o; o >>= 1) v += __shfl_down_sync(0xffffffffu, v, o);
    return v;
}

// ---------------- scratch (static device memory; no runtime allocs) ----------------
__device__ float  g_fpre[NPTS * HDIM];          // pre-norm features f
__device__ float4 g_f[NPTS * HDIM / 4];         // normalized f, [j][h]
__device__ float4 g_respart4[JSPLIT * NPTS * HDIM / 4]; // j-split partial results
__device__ float  g_opre[NPTS * ODIM];          // pre-norm output MLP
__device__ float  g_pin[32 * 8];                // per-block partial group stats (in)
__device__ float  g_pout[32 * 8];               // per-block partial group stats (out)
__device__ float2 g_statin[4];                  // (mu, rstd) per group (in)
__device__ float2 g_statout[4];                 // (mu, rstd) per group (out)

// ---------------- kernel 1: input MLP (16->64->64) + partial group stats ----------------
__global__ void k_infeat(const float* __restrict__ feat,
                         const float* __restrict__ W1, const float* __restrict__ b1,
                         const float* __restrict__ W2, const float* __restrict__ b2) {
    __shared__ float4 W1s[256];   // 64x16
    __shared__ float4 W2s[1024];  // 64x64
    __shared__ float  b1s[64], b2s[64];
    __shared__ float  red[4][8];
    int tid = threadIdx.x;
    for (int t = tid; t < 256;  t += 128) W1s[t] = ((const float4*)W1)[t];
    for (int t = tid; t < 1024; t += 128) W2s[t] = ((const float4*)W2)[t];
    if (tid < 64) { b1s[tid] = b1[tid]; b2s[tid] = b2[tid]; }
    __syncthreads();

    int p = blockIdx.x * 128 + tid;
    float f[16];
    #pragma unroll
    for (int k = 0; k < 16; k++) f[k] = feat[p * 16 + k];

    float t1[64];
    #pragma unroll
    for (int h = 0; h < 64; h++) {
        float s = b1s[h];
        #pragma unroll
        for (int k4 = 0; k4 < 4; k4++) {
            float4 w = W1s[h * 4 + k4];
            s = fmaf(w.x, f[k4*4+0], fmaf(w.y, f[k4*4+1], fmaf(w.z, f[k4*4+2], fmaf(w.w, f[k4*4+3], s))));
        }
        t1[h] = leaky(s);
    }

    float gs[4] = {0,0,0,0}, gq[4] = {0,0,0,0};
    for (int h = 0; h < 64; h++) {
        float s = b2s[h];
        #pragma unroll
        for (int k4 = 0; k4 < 16; k4++) {
            float4 w = W2s[h * 16 + k4];
            s = fmaf(w.x, t1[k4*4+0], fmaf(w.y, t1[k4*4+1], fmaf(w.z, t1[k4*4+2], fmaf(w.w, t1[k4*4+3], s))));
        }
        float v = leaky(s);
        g_fpre[p * 64 + h] = v;
        int g = h >> 4; gs[g] += v; gq[g] += v * v;
    }

    int w = tid >> 5, l = tid & 31;
    #pragma unroll
    for (int g = 0; g < 4; g++) {
        float s = warp_sum(gs[g]);
        float q = warp_sum(gq[g]);
        if (l == 0) { red[w][g*2] = s; red[w][g*2+1] = q; }
    }
    __syncthreads();
    if (tid < 8) g_pin[blockIdx.x * 8 + tid] = red[0][tid] + red[1][tid] + red[2][tid] + red[3][tid];
}

// ---------------- kernel 2/6: finalize group stats (deterministic fixed-order sum) ----------------
__global__ void k_finstat(int which) {
    int g = threadIdx.x;
    if (g < 4) {
        const float* pin = which ? g_pout : g_pin;
        float invc = which ? (1.0f / 16384.0f) : (1.0f / 65536.0f);
        float s = 0.f, q = 0.f;
        for (int b = 0; b < 32; b++) { s += pin[b*8 + g*2]; q += pin[b*8 + g*2 + 1]; }
        float mu  = s * invc;
        float var = q * invc - mu * mu;
        float2 st = make_float2(mu, rsqrtf(var + 1e-5f));
        if (which) g_statout[g] = st; else g_statin[g] = st;
    }
}

// ---------------- kernel 3: apply GroupNorm to f ----------------
__global__ void k_fnorm(const float* __restrict__ gin, const float* __restrict__ bin) {
    int idx = blockIdx.x * 256 + threadIdx.x;
    int h = idx & 63, g = h >> 4;
    float2 st = g_statin[g];
    float v = (g_fpre[idx] - st.x) * st.y;
    ((float*)g_f)[idx] = v * gin[h] + bin[h];
}

// ---------------- kernel 4: the pairwise convolution (dominant) ----------------
// Warp = 8 i's x 4 h-lanes (16 channels each). f32x2-packed A2 matvec + accumulate.
// relu via (x+|x|)*0.5 with the 0.5 folded into exp; B2 folded into first matvec step.
__global__ void __launch_bounds__(128) k_conv(
        const float* __restrict__ points, const float* __restrict__ nuvp,
        const float* __restrict__ A1, const float* __restrict__ B1,
        const float* __restrict__ A2, const float* __restrict__ B2) {
    __shared__ float4 sp[TJ], sn[TJ];
    __shared__ ull    sfq[TJ * 32];   // f tile as packed pairs: [j][hp], hp=0..31

    const float S   = 0.70710678118654752f;   // 1/(sqrt(2)*RADIUS)
    const float L2E = 1.4426950408889634f;    // log2(e)
    const ull ABS2  = 0x7fffffff7fffffffULL;

    int tid = threadIdx.x;
    int warp = tid >> 5, lane = tid & 31, isub = lane & 7, hl = lane >> 3;
    int i  = blockIdx.x * 32 + warp * 8 + isub;
    int h0 = hl * 16;

    float pix = points[3*i+0]*S, piy = points[3*i+1]*S, piz = points[3*i+2]*S;
    float nix = nuvp[9*i+0],     niy = nuvp[9*i+1],     niz = nuvp[9*i+2];
    float m2x = -2.0f*pix, m2y = -2.0f*piy, m2z = -2.0f*piz;
    float bsq = pix*pix + piy*piy + piz*piz;

    // M = A1 @ nuv_i  (8x3); bias bb = B1 - M . pi (folds the diff subtraction)
    float M[8][3], bb[8];
    #pragma unroll
    for (int c = 0; c < 8; c++) {
        float a0 = A1[c*3+0], a1 = A1[c*3+1], a2c = A1[c*3+2];
        #pragma unroll
        for (int d = 0; d < 3; d++)
            M[c][d] = fmaf(a0, nuvp[9*i + d], fmaf(a1, nuvp[9*i + 3 + d], a2c * nuvp[9*i + 6 + d]));
        bb[c] = B1[c] - (M[c][0]*pix + M[c][1]*piy + M[c][2]*piz);
    }

    // A2 slice for this lane's 16 channels, packed as h-pairs: a2r[c][hp]
    ull a2r[8][8];
    #pragma unroll
    for (int hp = 0; hp < 8; hp++)
        #pragma unroll
        for (int c = 0; c < 8; c++)
            a2r[c][hp] = pk(A2[(h0 + 2*hp) * 8 + c], A2[(h0 + 2*hp + 1) * 8 + c]);
    ull b2p[8];
    #pragma unroll
    for (int hp = 0; hp < 8; hp++) b2p[hp] = pk(B2[h0 + 2*hp], B2[h0 + 2*hp + 1]);

    ull acc[8];
    #pragma unroll
    for (int hp = 0; hp < 8; hp++) acc[hp] = pk(0.f, 0.f);

    int j0base = blockIdx.y * JRANGE;
    for (int jb = 0; jb < JRANGE; jb += TJ) {
        int j0 = j0base + jb;
        __syncthreads();
        for (int t = tid; t < TJ; t += 128) {
            int j = j0 + t;
            float px = points[3*j]*S, py = points[3*j+1]*S, pz = points[3*j+2]*S;
            sp[t] = make_float4(px, py, pz, px*px + py*py + pz*pz);
            sn[t] = make_float4(nuvp[9*j], nuvp[9*j+1], nuvp[9*j+2], 0.f);
        }
        for (int t = tid; t < TJ * 32; t += 128) sfq[t] = ((const ull*)g_f)[j0 * 32 + t];
        __syncthreads();

        #pragma unroll 1
        for (int jj = 0; jj < TJ; jj++) {
            float4 pj = sp[jj], nj = sn[jj];
            // window/2 = exp2(-sq*(2-dot)^2*log2e - 1)
            float sq = fmaf(m2x, pj.x, fmaf(m2y, pj.y, fmaf(m2z, pj.z, bsq + pj.w)));
            float dt = fmaf(nix, nj.x, fmaf(niy, nj.y, niz * nj.z));
            float t2 = 2.0f - dt;
            float u  = t2 * t2;
            float v  = sq * u;
            float w2 = ex2(fmaf(v, -L2E, -1.0f));
            ull ws2  = pk(w2, w2);

            // Y = relu(M . pj + bb), broadcast-packed
            ull ys[8];
            #pragma unroll
            for (int c = 0; c < 8; c++) {
                float y = fmaf(M[c][0], pj.x, fmaf(M[c][1], pj.y, fmaf(M[c][2], pj.z, bb[c])));
                y = fmaxf(y, 0.f);
                ys[c] = pk(y, y);
            }

            // G = A2 . Y + B2 : 8 independent chains, B2 folded into c=0
            ull g[8];
            #pragma unroll
            for (int hp = 0; hp < 8; hp++) g[hp] = fma2(a2r[0][hp], ys[0], b2p[hp]);
            #pragma unroll
            for (int c = 1; c < 8; c++)
                #pragma unroll
                for (int hp = 0; hp < 8; hp++) g[hp] = fma2(a2r[c][hp], ys[c], g[hp]);

            // acc += relu(G) * f * w  ==  (G+|G|) * f * (w/2)
            const ull* frow = sfq + jj * 32 + hl * 8;
            #pragma unroll
            for (int hp = 0; hp < 8; hp++) {
                ull ab = g[hp] & ABS2;
                ull s  = add2(ab, g[hp]);
                ull p  = mul2(s, frow[hp]);
                acc[hp] = fma2(p, ws2, acc[hp]);
            }
        }
    }

    float* rp = ((float*)g_respart4) + ((size_t)blockIdx.y * NPTS + i) * 64 + h0;
    #pragma unroll
    for (int hp = 0; hp < 8; hp++) {
        float a, b; upk(acc[hp], a, b);
        rp[2*hp] = a; rp[2*hp+1] = b;
    }
}

// ---------------- kernel 5: reduce j-splits + output MLP (64->16->16) + partial stats ----------------
__global__ void k_outfeat(const float* __restrict__ W1, const float* __restrict__ b1,
                          const float* __restrict__ W2, const float* __restrict__ b2) {
    __shared__ float4 W1s[256];  // 16x64
    __shared__ float4 W2s[64];   // 16x16
    __shared__ float  b1s[16], b2s[16];
    __shared__ float  red[4][8];
    int tid = threadIdx.x;
    for (int t = tid; t < 256; t += 128) W1s[t] = ((const float4*)W1)[t];
    if (tid < 64) W2s[tid] = ((const float4*)W2)[tid];
    if (tid < 16) { b1s[tid] = b1[tid]; b2s[tid] = b2[tid]; }
    __syncthreads();

    int p = blockIdx.x * 128 + tid;
    float4 r4[16];
    #pragma unroll
    for (int k = 0; k < 16; k++) r4[k] = g_respart4[(size_t)p * 16 + k];
    for (int s = 1; s < JSPLIT; s++)
        #pragma unroll
        for (int k = 0; k < 16; k++) {
            float4 v = g_respart4[((size_t)s * NPTS + p) * 16 + k];
            r4[k].x += v.x; r4[k].y += v.y; r4[k].z += v.z; r4[k].w += v.w;
        }

    float o1[16];
    #pragma unroll
    for (int h = 0; h < 16; h++) {
        float s = b1s[h];
        #pragma unroll
        for (int k = 0; k < 16; k++) {
            float4 w = W1s[h * 16 + k]; float4 v = r4[k];
            s = fmaf(w.x, v.x, fmaf(w.y, v.y, fmaf(w.z, v.z, fmaf(w.w, v.w, s))));
        }
        o1[h] = leaky(s);
    }

    float gs[4] = {0,0,0,0}, gq[4] = {0,0,0,0};
    #pragma unroll
    for (int h = 0; h < 16; h++) {
        float s = b2s[h];
        #pragma unroll
        for (int k4 = 0; k4 < 4; k4++) {
            float4 w = W2s[h * 4 + k4];
            s = fmaf(w.x, o1[k4*4+0], fmaf(w.y, o1[k4*4+1], fmaf(w.z, o1[k4*4+2], fmaf(w.w, o1[k4*4+3], s))));
        }
        float v = leaky(s);
        g_opre[p * 16 + h] = v;
        int g = h >> 2; gs[g] += v; gq[g] += v * v;
    }

    int w = tid >> 5, l = tid & 31;
    #pragma unroll
    for (int g = 0; g < 4; g++) {
        float s = warp_sum(gs[g]);
        float q = warp_sum(gq[g]);
        if (l == 0) { red[w][g*2] = s; red[w][g*2+1] = q; }
    }
    __syncthreads();
    if (tid < 8) g_pout[blockIdx.x * 8 + tid] = red[0][tid] + red[1][tid] + red[2][tid] + red[3][tid];
}

// ---------------- kernel 7: final GroupNorm -> d_out ----------------
__global__ void k_onorm(float* __restrict__ out,
                        const float* __restrict__ gout, const float* __restrict__ bout) {
    int idx = blockIdx.x * 256 + threadIdx.x;
    int h = idx & 15, g = h >> 2;
    float2 st = g_statout[g];
    out[idx] = (g_opre[idx] - st.x) * st.y * gout[h] + bout[h];
}

// ---------------- launch ----------------
extern "C" void kernel_launch(void* const* d_in, const int* in_sizes, int n_in,
                              void* d_out, int out_size) {
    const float* points   = (const float*)d_in[0];
    const float* nuv      = (const float*)d_in[1];
    const float* features = (const float*)d_in[2];
    const float* W_in1    = (const float*)d_in[3];
    const float* b_in1    = (const float*)d_in[4];
    const float* W_in2    = (const float*)d_in[5];
    const float* b_in2    = (const float*)d_in[6];
    const float* g_in     = (const float*)d_in[7];
    const float* beta_in  = (const float*)d_in[8];
    const float* A1       = (const float*)d_in[9];
    const float* B1       = (const float*)d_in[10];
    const float* A2       = (const float*)d_in[11];
    const float* B2       = (const float*)d_in[12];
    const float* W_out1   = (const float*)d_in[13];
    const float* b_out1   = (const float*)d_in[14];
    const float* W_out2   = (const float*)d_in[15];
    const float* b_out2   = (const float*)d_in[16];
    const float* g_out    = (const float*)d_in[17];
    const float* beta_out = (const float*)d_in[18];
    float* out = (float*)d_out;

    k_infeat <<<32, 128>>>(features, W_in1, b_in1, W_in2, b_in2);
    k_finstat<<<1, 32>>>(0);
    k_fnorm  <<<NPTS * HDIM / 256, 256>>>(g_in, beta_in);
    k_conv   <<<dim3(NPTS / 32, JSPLIT), 128>>>(points, nuv, A1, B1, A2, B2);
    k_outfeat<<<32, 128>>>(W_out1, b_out1, W_out2, b_out2);
    k_finstat<<<1, 32>>>(1);
    k_onorm  <<<NPTS * ODIM / 256, 256>>>(out, g_out, beta_out);
}

// round 3
// speedup vs baseline: 1.0529x; 1.0529x over previous
#include <cuda_runtime.h>

// ---------------- problem dims ----------------
#define NPTS   4096
#define HDIM   64
#define ODIM   16
#define JSPLIT 16
#define TJ     128
#define JS     32
#define JRANGE (NPTS / JSPLIT)

typedef unsigned long long ull;

// dynamic smem layout for k_conv
#define OFF_SFQ   0
#define OFF_SP    32768
#define OFF_SN    34816
#define OFF_SY    36864
#define OFF_SW    (36864 + 65536)
#define OFF_ICON  (OFF_SW + 4096)
#define SMEM_DYN  (OFF_ICON + 32 * 20 * 8)   // 111616 B

// ---------------- f32x2 helpers ----------------
static __device__ __forceinline__ ull pk(float a, float b) {
    ull r; asm("mov.b64 %0, {%1, %2};" : "=l"(r) : "f"(a), "f"(b)); return r;
}
static __device__ __forceinline__ void upk(ull x, float& a, float& b) {
    asm("mov.b64 {%0, %1}, %2;" : "=f"(a), "=f"(b) : "l"(x));
}
static __device__ __forceinline__ ull fma2(ull a, ull b, ull c) {
    ull d; asm("fma.rn.f32x2 %0, %1, %2, %3;" : "=l"(d) : "l"(a), "l"(b), "l"(c)); return d;
}
static __device__ __forceinline__ ull mul2(ull a, ull b) {
    ull d; asm("mul.rn.f32x2 %0, %1, %2;" : "=l"(d) : "l"(a), "l"(b)); return d;
}
static __device__ __forceinline__ float ex2(float x) {
    float r; asm("ex2.approx.f32 %0, %1;" : "=f"(r) : "f"(x)); return r;
}
static __device__ __forceinline__ float leaky(float x) { return fmaxf(x, 0.2f * x); }

static __device__ __forceinline__ float warp_sum(float v) {
    #pragma unroll
    for (int o = 16; o; o >>= 1) v += __shfl_down_sync(0xffffffffu, v, o);
    return v;
}

// ---------------- scratch ----------------
__device__ float  g_fpre[NPTS * HDIM];
__device__ float4 g_f[NPTS * HDIM / 4];
__device__ float4 g_respart4[JSPLIT * NPTS * HDIM / 4];
__device__ float  g_opre[NPTS * ODIM];
__device__ float  g_pin[32 * 8];
__device__ float  g_pout[32 * 8];
__device__ float2 g_statin[4];
__device__ float2 g_statout[4];

// ---------------- kernel 1: input MLP (16->64->64) + partial group stats ----------------
__global__ void k_infeat(const float* __restrict__ feat,
                         const float* __restrict__ W1, const float* __restrict__ b1,
                         const float* __restrict__ W2, const float* __restrict__ b2) {
    __shared__ float4 W1s[256];
    __shared__ float4 W2s[1024];
    __shared__ float  b1s[64], b2s[64];
    __shared__ float  red[4][8];
    int tid = threadIdx.x;
    for (int t = tid; t < 256;  t += 128) W1s[t] = ((const float4*)W1)[t];
    for (int t = tid; t < 1024; t += 128) W2s[t] = ((const float4*)W2)[t];
    if (tid < 64) { b1s[tid] = b1[tid]; b2s[tid] = b2[tid]; }
    __syncthreads();

    int p = blockIdx.x * 128 + tid;
    float f[16];
    #pragma unroll
    for (int k = 0; k < 16; k++) f[k] = feat[p * 16 + k];

    float t1[64];
    #pragma unroll
    for (int h = 0; h < 64; h++) {
        float s = b1s[h];
        #pragma unroll
        for (int k4 = 0; k4 < 4; k4++) {
            float4 w = W1s[h * 4 + k4];
            s = fmaf(w.x, f[k4*4+0], fmaf(w.y, f[k4*4+1], fmaf(w.z, f[k4*4+2], fmaf(w.w, f[k4*4+3], s))));
        }
        t1[h] = leaky(s);
    }

    float gs[4] = {0,0,0,0}, gq[4] = {0,0,0,0};
    for (int h = 0; h < 64; h++) {
        float s = b2s[h];
        #pragma unroll
        for (int k4 = 0; k4 < 16; k4++) {
            float4 w = W2s[h * 16 + k4];
            s = fmaf(w.x, t1[k4*4+0], fmaf(w.y, t1[k4*4+1], fmaf(w.z, t1[k4*4+2], fmaf(w.w, t1[k4*4+3], s))));
        }
        float v = leaky(s);
        g_fpre[p * 64 + h] = v;
        int g = h >> 4; gs[g] += v; gq[g] += v * v;
    }

    int w = tid >> 5, l = tid & 31;
    #pragma unroll
    for (int g = 0; g < 4; g++) {
        float s = warp_sum(gs[g]);
        float q = warp_sum(gq[g]);
        if (l == 0) { red[w][g*2] = s; red[w][g*2+1] = q; }
    }
    __syncthreads();
    if (tid < 8) g_pin[blockIdx.x * 8 + tid] = red[0][tid] + red[1][tid] + red[2][tid] + red[3][tid];
}

// ---------------- kernel 2/6: finalize group stats ----------------
__global__ void k_finstat(int which) {
    int g = threadIdx.x;
    if (g < 4) {
        const float* pin = which ? g_pout : g_pin;
        float invc = which ? (1.0f / 16384.0f) : (1.0f / 65536.0f);
        float s = 0.f, q = 0.f;
        for (int b = 0; b < 32; b++) { s += pin[b*8 + g*2]; q += pin[b*8 + g*2 + 1]; }
        float mu  = s * invc;
        float var = q * invc - mu * mu;
        float2 st = make_float2(mu, rsqrtf(var + 1e-5f));
        if (which) g_statout[g] = st; else g_statin[g] = st;
    }
}

// ---------------- kernel 3: apply GroupNorm to f ----------------
__global__ void k_fnorm(const float* __restrict__ gin, const float* __restrict__ bin) {
    int idx = blockIdx.x * 256 + threadIdx.x;
    int h = idx & 63, g = h >> 4;
    float2 st = g_statin[g];
    float v = (g_fpre[idx] - st.x) * st.y;
    ((float*)g_f)[idx] = v * gin[h] + bin[h];
}

// ---------------- kernel 4: pairwise convolution ----------------
// Phase A (cooperative): per (i,j) pair compute window w and Y[8] once, store
// Y pre-duplicated as (y,y) f32x2 pairs in smem.  Phase B: per-lane 16-channel
// A2 matvec (f32x2) + FMNMX relu + weighted f accumulate.
__global__ void __launch_bounds__(128, 2) k_conv(
        const float* __restrict__ points, const float* __restrict__ nuvp,
        const float* __restrict__ A1, const float* __restrict__ B1,
        const float* __restrict__ A2, const float* __restrict__ B2) {
    extern __shared__ char smem[];
    ull*    sfq  = (ull*)   (smem + OFF_SFQ);   // [jt 0..127][hp 0..31] packed f
    float4* sp   = (float4*)(smem + OFF_SP);    // [jt] (px,py,pz,|p|^2) scaled
    float4* sn   = (float4*)(smem + OFF_SN);    // [jt] normal
    ull*    sY   = (ull*)   (smem + OFF_SY);    // [jl 0..31][c 0..7][il 0..31] (y,y)
    float*  sW   = (float*) (smem + OFF_SW);    // [jl][il]
    ull*    icon = (ull*)   (smem + OFF_ICON);  // [il][20] per-i constants

    const float S   = 0.70710678118654752f;
    const float L2E = 1.4426950408889634f;

    int tid  = threadIdx.x;
    int warp = tid >> 5, lane = tid & 31;
    int isub = lane & 7, hl = lane >> 3;
    int ilB  = warp * 8 + isub;               // phase-B block-local i
    int ilA  = lane;                          // phase-A block-local i
    int jg   = warp;                          // phase-A j-group
    int h0   = hl * 16;

    // ---- per-i constants into smem (threads 0..31) ----
    if (tid < 32) {
        int ii = blockIdx.x * 32 + tid;
        float pix = points[3*ii+0]*S, piy = points[3*ii+1]*S, piz = points[3*ii+2]*S;
        float nx = nuvp[9*ii+0], ny = nuvp[9*ii+1], nz = nuvp[9*ii+2];
        float M[8][3], bb[8];
        #pragma unroll
        for (int c = 0; c < 8; c++) {
            float a0 = A1[c*3+0], a1 = A1[c*3+1], a2c = A1[c*3+2];
            #pragma unroll
            for (int d = 0; d < 3; d++)
                M[c][d] = fmaf(a0, nuvp[9*ii + d], fmaf(a1, nuvp[9*ii + 3 + d], a2c * nuvp[9*ii + 6 + d]));
            bb[c] = B1[c] - (M[c][0]*pix + M[c][1]*piy + M[c][2]*piz);
        }
        ull* ic = icon + tid * 20;
        #pragma unroll
        for (int cp = 0; cp < 4; cp++) {
            ic[cp]      = pk(M[2*cp][0], M[2*cp+1][0]);
            ic[4 + cp]  = pk(M[2*cp][1], M[2*cp+1][1]);
            ic[8 + cp]  = pk(M[2*cp][2], M[2*cp+1][2]);
            ic[12 + cp] = pk(bb[2*cp],  bb[2*cp+1]);
        }
        ic[16] = pk(-2.0f*pix, -2.0f*piy);
        ic[17] = pk(-2.0f*piz, pix*pix + piy*piy + piz*piz);
        ic[18] = pk(nx, ny);
        ic[19] = pk(nz, 0.f);
    }

    // ---- per-lane A2 slice (h-pairs) ----
    ull a2r[8][8];
    #pragma unroll
    for (int hp = 0; hp < 8; hp++)
        #pragma unroll
        for (int c = 0; c < 8; c++)
            a2r[c][hp] = pk(A2[(h0 + 2*hp) * 8 + c], A2[(h0 + 2*hp + 1) * 8 + c]);
    ull b2p[8];
    #pragma unroll
    for (int hp = 0; hp < 8; hp++) b2p[hp] = pk(B2[h0 + 2*hp], B2[h0 + 2*hp + 1]);

    ull acc[8];
    #pragma unroll
    for (int hp = 0; hp < 8; hp++) acc[hp] = pk(0.f, 0.f);

    __syncthreads();   // icon ready

    int j0base = blockIdx.y * JRANGE;
    for (int jb = 0; jb < JRANGE; jb += TJ) {
        int j0 = j0base + jb;
        // tile load (previous consumers finished at subtile-end sync)
        {
            int j = j0 + tid;
            float px = points[3*j]*S, py = points[3*j+1]*S, pz = points[3*j+2]*S;
            sp[tid] = make_float4(px, py, pz, px*px + py*py + pz*pz);
            sn[tid] = make_float4(nuvp[9*j], nuvp[9*j+1], nuvp[9*j+2], 0.f);
        }
        for (int t = tid; t < TJ * 32; t += 128) sfq[t] = ((const ull*)g_f)[j0 * 32 + t];
        __syncthreads();

        for (int s = 0; s < TJ; s += JS) {
            // ---------- phase A ----------
            {
                const ull* ic = icon + ilA * 20;
                ull Ic[16];
                #pragma unroll
                for (int k = 0; k < 16; k++) Ic[k] = ic[k];
                float m2x, m2y, m2z, bsq, nix, niy, niz, dum;
                upk(ic[16], m2x, m2y); upk(ic[17], m2z, bsq);
                upk(ic[18], nix, niy); upk(ic[19], niz, dum);

                #pragma unroll
                for (int q = 0; q < 8; q++) {
                    int jl = jg * 8 + q;
                    float4 pj = sp[s + jl];
                    float4 nj = sn[s + jl];
                    float sq = fmaf(m2x, pj.x, fmaf(m2y, pj.y, fmaf(m2z, pj.z, bsq + pj.w)));
                    float dt = fmaf(nix, nj.x, fmaf(niy, nj.y, niz * nj.z));
                    float t2 = 2.0f - dt;
                    float wv = ex2(sq * t2 * t2 * (-L2E));
                    sW[jl * 32 + ilA] = wv;
                    ull px2 = pk(pj.x, pj.x), py2 = pk(pj.y, pj.y), pz2 = pk(pj.z, pj.z);
                    #pragma unroll
                    for (int cp = 0; cp < 4; cp++) {
                        ull y2 = fma2(Ic[cp], px2, fma2(Ic[4+cp], py2, fma2(Ic[8+cp], pz2, Ic[12+cp])));
                        float a, b; upk(y2, a, b);
                        a = fmaxf(a, 0.f); b = fmaxf(b, 0.f);
                        int base = (jl * 8 + 2 * cp) * 32 + ilA;
                        sY[base]      = pk(a, a);
                        sY[base + 32] = pk(b, b);
                    }
                }
            }
            __syncthreads();

            // ---------- phase B ----------
            #pragma unroll 1
            for (int jj = 0; jj < JS; jj++) {
                float wv = sW[jj * 32 + ilB];
                const ull* yp = sY + jj * 256 + ilB;
                ull ys0 = yp[0],   ys1 = yp[32],  ys2 = yp[64],  ys3 = yp[96];
                ull ys4 = yp[128], ys5 = yp[160], ys6 = yp[192], ys7 = yp[224];
                const ull* frow = sfq + (s + jj) * 32 + hl * 8;

                ull g[8];
                #pragma unroll
                for (int hp = 0; hp < 8; hp++) g[hp] = fma2(a2r[0][hp], ys0, b2p[hp]);
                #pragma unroll
                for (int hp = 0; hp < 8; hp++) g[hp] = fma2(a2r[1][hp], ys1, g[hp]);
                #pragma unroll
                for (int hp = 0; hp < 8; hp++) g[hp] = fma2(a2r[2][hp], ys2, g[hp]);
                #pragma unroll
                for (int hp = 0; hp < 8; hp++) g[hp] = fma2(a2r[3][hp], ys3, g[hp]);
                #pragma unroll
                for (int hp = 0; hp < 8; hp++) g[hp] = fma2(a2r[4][hp], ys4, g[hp]);
                #pragma unroll
                for (int hp = 0; hp < 8; hp++) g[hp] = fma2(a2r[5][hp], ys5, g[hp]);
                #pragma unroll
                for (int hp = 0; hp < 8; hp++) g[hp] = fma2(a2r[6][hp], ys6, g[hp]);
                #pragma unroll
                for (int hp = 0; hp < 8; hp++) g[hp] = fma2(a2r[7][hp], ys7, g[hp]);

                ull ws = pk(wv, wv);
                #pragma unroll
                for (int hp = 0; hp < 8; hp++) {
                    float a, b; upk(g[hp], a, b);
                    a = fmaxf(a, 0.f); b = fmaxf(b, 0.f);
                    acc[hp] = fma2(mul2(pk(a, b), frow[hp]), ws, acc[hp]);
                }
            }
            __syncthreads();
        }
    }

    int i = blockIdx.x * 32 + ilB;
    float* rp = ((float*)g_respart4) + ((size_t)blockIdx.y * NPTS + i) * 64 + h0;
    #pragma unroll
    for (int hp = 0; hp < 8; hp++) {
        float a, b; upk(acc[hp], a, b);
        rp[2*hp] = a; rp[2*hp+1] = b;
    }
}

// ---------------- kernel 5: reduce j-splits + output MLP + partial stats ----------------
__global__ void k_outfeat(const float* __restrict__ W1, const float* __restrict__ b1,
                          const float* __restrict__ W2, const float* __restrict__ b2) {
    __shared__ float4 W1s[256];
    __shared__ float4 W2s[64];
    __shared__ float  b1s[16], b2s[16];
    __shared__ float  red[4][8];
    int tid = threadIdx.x;
    for (int t = tid; t < 256; t += 128) W1s[t] = ((const float4*)W1)[t];
    if (tid < 64) W2s[tid] = ((const float4*)W2)[tid];
    if (tid < 16) { b1s[tid] = b1[tid]; b2s[tid] = b2[tid]; }
    __syncthreads();

    int p = blockIdx.x * 128 + tid;
    float4 r4[16];
    #pragma unroll
    for (int k = 0; k < 16; k++) r4[k] = g_respart4[(size_t)p * 16 + k];
    for (int s = 1; s < JSPLIT; s++)
        #pragma unroll
        for (int k = 0; k < 16; k++) {
            float4 v = g_respart4[((size_t)s * NPTS + p) * 16 + k];
            r4[k].x += v.x; r4[k].y += v.y; r4[k].z += v.z; r4[k].w += v.w;
        }

    float o1[16];
    #pragma unroll
    for (int h = 0; h < 16; h++) {
        float s = b1s[h];
        #pragma unroll
        for (int k = 0; k < 16; k++) {
            float4 w = W1s[h * 16 + k]; float4 v = r4[k];
            s = fmaf(w.x, v.x, fmaf(w.y, v.y, fmaf(w.z, v.z, fmaf(w.w, v.w, s))));
        }
        o1[h] = leaky(s);
    }

    float gs[4] = {0,0,0,0}, gq[4] = {0,0,0,0};
    #pragma unroll
    for (int h = 0; h < 16; h++) {
        float s = b2s[h];
        #pragma unroll
        for (int k4 = 0; k4 < 4; k4++) {
            float4 w = W2s[h * 4 + k4];
            s = fmaf(w.x, o1[k4*4+0], fmaf(w.y, o1[k4*4+1], fmaf(w.z, o1[k4*4+2], fmaf(w.w, o1[k4*4+3], s))));
        }
        float v = leaky(s);
        g_opre[p * 16 + h] = v;
        int g = h >> 2; gs[g] += v; gq[g] += v * v;
    }

    int w = tid >> 5, l = tid & 31;
    #pragma unroll
    for (int g = 0; g < 4; g++) {
        float s = warp_sum(gs[g]);
        float q = warp_sum(gq[g]);
        if (l == 0) { red[w][g*2] = s; red[w][g*2+1] = q; }
    }
    __syncthreads();
    if (tid < 8) g_pout[blockIdx.x * 8 + tid] = red[0][tid] + red[1][tid] + red[2][tid] + red[3][tid];
}

// ---------------- kernel 7: final GroupNorm -> d_out ----------------
__global__ void k_onorm(float* __restrict__ out,
                        const float* __restrict__ gout, const float* __restrict__ bout) {
    int idx = blockIdx.x * 256 + threadIdx.x;
    int h = idx & 15, g = h >> 2;
    float2 st = g_statout[g];
    out[idx] = (g_opre[idx] - st.x) * st.y * gout[h] + bout[h];
}

// ---------------- launch ----------------
extern "C" void kernel_launch(void* const* d_in, const int* in_sizes, int n_in,
                              void* d_out, int out_size) {
    const float* points   = (const float*)d_in[0];
    const float* nuv      = (const float*)d_in[1];
    const float* features = (const float*)d_in[2];
    const float* W_in1    = (const float*)d_in[3];
    const float* b_in1    = (const float*)d_in[4];
    const float* W_in2    = (const float*)d_in[5];
    const float* b_in2    = (const float*)d_in[6];
    const float* g_in     = (const float*)d_in[7];
    const float* beta_in  = (const float*)d_in[8];
    const float* A1       = (const float*)d_in[9];
    const float* B1       = (const float*)d_in[10];
    const float* A2       = (const float*)d_in[11];
    const float* B2       = (const float*)d_in[12];
    const float* W_out1   = (const float*)d_in[13];
    const float* b_out1   = (const float*)d_in[14];
    const float* W_out2   = (const float*)d_in[15];
    const float* b_out2   = (const float*)d_in[16];
    const float* g_out    = (const float*)d_in[17];
    const float* beta_out = (const float*)d_in[18];
    float* out = (float*)d_out;

    static int smem_set = 0;
    if (!smem_set) {
        cudaFuncSetAttribute(k_conv, cudaFuncAttributeMaxDynamicSharedMemorySize, SMEM_DYN);
        smem_set = 1;
    }

    k_infeat <<<32, 128>>>(features, W_in1, b_in1, W_in2, b_in2);
    k_finstat<<<1, 32>>>(0);
    k_fnorm  <<<NPTS * HDIM / 256, 256>>>(g_in, beta_in);
    k_conv   <<<dim3(NPTS / 32, JSPLIT), 128, SMEM_DYN>>>(points, nuv, A1, B1, A2, B2);
    k_outfeat<<<32, 128>>>(W_out1, b_out1, W_out2, b_out2);
    k_finstat<<<1, 32>>>(1);
    k_onorm  <<<NPTS * ODIM / 256, 256>>>(out, g_out, beta_out);
}